// round 4
// baseline (speedup 1.0000x reference)
#include <cuda_runtime.h>
#include <cstddef>

// Problem constants
#define NB   16
#define NT   64
#define NF0  8
#define NN   100
#define BT   (NB * NT)            // 1024
#define ROWSTRIDE (NF0 * NN)      // 800 floats per (b,t) slice
#define SLAB ((size_t)BT * ROWSTRIDE)  // 819200 floats per k-slab

// Diffusion scratch: z_k for k = 1..15 at slab k-1.
// Triangular region t<k is never written; head substitutes zeros there.
__device__ float g_z[15 * BT * ROWSTRIDE];   // ~49.15 MB

// ---------------------------------------------------------------------------
// Diffusion step k: z_k[b,t] = z_{k-1}[b,t-1] @ S[b,t]  (skip t<k entirely).
// One block per (b,t), 256 threads (200 active), tile 1 f-row x 4 m-cols.
// A in smem, S rows streamed as float4 (L2-resident across launches).
// ---------------------------------------------------------------------------
__global__ __launch_bounds__(256)
void diffuse_step_kernel(const float* __restrict__ x,
                         const float* __restrict__ S,
                         int k)
{
    int bt  = blockIdx.x;          // b*64 + t
    int t   = bt & 63;
    if (t < k) return;             // zero region: never stored
    int tid = threadIdx.x;

    const float* src = (k == 1)
        ? (x + (size_t)(bt - 1) * ROWSTRIDE)
        : (g_z + (size_t)(k - 2) * SLAB + (size_t)(bt - 1) * ROWSTRIDE);

    __shared__ float Ash[ROWSTRIDE];
    for (int i = tid; i < ROWSTRIDE; i += 256) Ash[i] = src[i];
    __syncthreads();

    if (tid < 200) {
        int mg = tid % 25;                       // m-quad
        int f  = tid / 25;                       // f-row 0..7
        int m0 = mg * 4;
        const float* A0 = Ash + f * NN;
        const float* Sp = S + (size_t)bt * (NN * NN) + m0;

        float a0 = 0.f, a1 = 0.f, a2 = 0.f, a3 = 0.f;
        #pragma unroll 5
        for (int n = 0; n < NN; n++) {
            float4 s = *reinterpret_cast<const float4*>(Sp + (size_t)n * NN);
            float va = A0[n];
            a0 = fmaf(va, s.x, a0); a1 = fmaf(va, s.y, a1);
            a2 = fmaf(va, s.z, a2); a3 = fmaf(va, s.w, a3);
        }
        float* d = g_z + (size_t)(k - 1) * SLAB + (size_t)bt * ROWSTRIDE
                 + f * NN + m0;
        d[0] = a0; d[1] = a1; d[2] = a2; d[3] = a3;
    }
}

// ---------------------------------------------------------------------------
// Fused head: gather z row [8][16] -> conv1(K=4)+relu+pool2 -> [32][6]
//             -> conv2(K=3)+relu+pool2 -> [64][2] -> fc1(128->64)+relu
//             -> fc2(64->5) -> out[b,t,o,n]
// 32 rows/block, 256 threads, 3 blocks/SM.
// Smem (floats): [0,4128) zsh (32x129) reused as y2sh
//                [4128,10304) y1sh (32x193), later aliased as hsh (32x65)
//                [10304,11328) w1   [11328,11360) b1
//                [11360,17504) w2   [17504,17568) b2
// fc1/fc2 weights read directly from global (L1 broadcast).
// ---------------------------------------------------------------------------
#define ZS   129
#define Y1S  193
#define Y2S  129
#define HS   65
#define OFF_Y1  4128
#define OFF_W1  10304
#define OFF_B1  11328
#define OFF_W2  11360
#define OFF_B2  17504
#define SMEM_FLOATS 17568

__global__ __launch_bounds__(256, 3)
void head_kernel(const float* __restrict__ x,
                 const float* __restrict__ w1g, const float* __restrict__ b1g,
                 const float* __restrict__ w2g, const float* __restrict__ b2g,
                 const float* __restrict__ f1wg, const float* __restrict__ f1bg,
                 const float* __restrict__ f2wg, const float* __restrict__ f2bg,
                 float* __restrict__ out)
{
    extern __shared__ float sm[];
    float* zsh  = sm;
    float* y2sh = sm;                 // reuses zsh region after conv1
    float* y1sh = sm + OFF_Y1;
    float* hsh  = sm + OFF_Y1;        // aliases y1sh (dead after conv2)
    float* w1sh = sm + OFF_W1;
    float* b1sh = sm + OFF_B1;
    float* w2sh = sm + OFF_W2;
    float* b2sh = sm + OFF_B2;

    int tid  = threadIdx.x;
    int row0 = blockIdx.x * 32;       // global row = (b*T + t)*N + n

    // ---- stage 0: gather z tile (32 rows x 8 f x 16 k = 4096) + weights ----
    for (int i = tid; i < 4096; i += 256) {
        int r  = i & 31;
        int kf = i >> 5;              // 0..127
        int f  = kf >> 4;             // 0..7
        int k  = kf & 15;             // 0..15
        int R  = row0 + r;
        int n  = R % NN;
        int bt = R / NN;
        float v;
        if (k == 0) {
            v = x[(size_t)bt * ROWSTRIDE + f * NN + n];
        } else if ((bt & 63) < k) {
            v = 0.f;                  // triangular zero region (never stored)
        } else {
            v = g_z[(size_t)(k - 1) * SLAB + (size_t)bt * ROWSTRIDE + f * NN + n];
        }
        zsh[r * ZS + f * 16 + k] = v;
    }
    for (int i = tid; i < 1024; i += 256) w1sh[i] = w1g[i];
    if (tid < 32) b1sh[tid] = b1g[tid];
    for (int i = tid; i < 6144; i += 256) w2sh[i] = w2g[i];
    if (tid < 64) b2sh[tid] = b2g[tid];
    __syncthreads();

    // ---- conv1 + relu + maxpool2 : thread = (r, fg), 2 channels x 2 passes ----
    {
        int r = tid & 31, fg = tid >> 5;         // fg in [0,8)
        #pragma unroll
        for (int p = 0; p < 2; p++) {            // channel pair pass
            int c0 = fg * 4 + p * 2;             // channels c0, c0+1
            float acc[2][12];
            #pragma unroll
            for (int c = 0; c < 2; c++)
                #pragma unroll
                for (int l = 0; l < 12; l++) acc[c][l] = 0.f;

            #pragma unroll 2
            for (int f0 = 0; f0 < 8; f0++) {
                float a[16];
                #pragma unroll
                for (int i = 0; i < 16; i++) a[i] = zsh[r * ZS + f0 * 16 + i];
                #pragma unroll
                for (int kk = 0; kk < 4; kk++) {
                    #pragma unroll
                    for (int c = 0; c < 2; c++) {
                        float w = w1sh[(c0 + c) * 32 + f0 * 4 + kk];
                        #pragma unroll
                        for (int l = 0; l < 12; l++)
                            acc[c][l] = fmaf(a[l + kk], w, acc[c][l]);
                    }
                }
            }
            #pragma unroll
            for (int c = 0; c < 2; c++) {
                int f1 = c0 + c;
                float bb = b1sh[f1];
                #pragma unroll
                for (int lp = 0; lp < 6; lp++) {
                    float v0 = fmaxf(acc[c][2 * lp]     + bb, 0.f);
                    float v1 = fmaxf(acc[c][2 * lp + 1] + bb, 0.f);
                    y1sh[r * Y1S + f1 * 6 + lp] = fmaxf(v0, v1);
                }
            }
        }
    }
    __syncthreads();

    // ---- conv2 + relu + maxpool2 : thread = (r, 8 channels) ----
    {
        int r = tid & 31, fg = tid >> 5;       // channels fg*8..+7
        float acc[8][4];
        #pragma unroll
        for (int c = 0; c < 8; c++)
            #pragma unroll
            for (int l = 0; l < 4; l++) acc[c][l] = 0.f;

        #pragma unroll 4
        for (int f1 = 0; f1 < 32; f1++) {
            float a[6];
            #pragma unroll
            for (int i = 0; i < 6; i++) a[i] = y1sh[r * Y1S + f1 * 6 + i];
            #pragma unroll
            for (int kk = 0; kk < 3; kk++) {
                #pragma unroll
                for (int c = 0; c < 8; c++) {
                    float w = w2sh[(fg * 8 + c) * 96 + f1 * 3 + kk];
                    #pragma unroll
                    for (int l = 0; l < 4; l++)
                        acc[c][l] = fmaf(a[l + kk], w, acc[c][l]);
                }
            }
        }
        __syncthreads();                       // y1 dead; safe to alias as hsh later
        #pragma unroll
        for (int c = 0; c < 8; c++) {
            int f2 = fg * 8 + c;
            float bb = b2sh[f2];
            float v0 = fmaxf(fmaxf(acc[c][0] + bb, 0.f), fmaxf(acc[c][1] + bb, 0.f));
            float v1 = fmaxf(fmaxf(acc[c][2] + bb, 0.f), fmaxf(acc[c][3] + bb, 0.f));
            y2sh[r * Y2S + f2 * 2 + 0] = v0;   // flatten order d = f2*2 + l
            y2sh[r * Y2S + f2 * 2 + 1] = v1;
        }
    }
    __syncthreads();

    // ---- fc1 + relu : 256 threads, tile 2 rows x 4 hidden, weights from L1 ----
    {
        int rg = tid & 15;                     // rows rg*2, rg*2+1
        int hg = tid >> 4;                     // hidden hg*4..+3
        const float* wrow = f1wg + (hg * 4) * 128;
        float acc[2][4];
        #pragma unroll
        for (int i = 0; i < 2; i++)
            #pragma unroll
            for (int j = 0; j < 4; j++) acc[i][j] = 0.f;

        #pragma unroll 4
        for (int d = 0; d < 128; d++) {
            float a0 = y2sh[(rg * 2 + 0) * Y2S + d];
            float a1 = y2sh[(rg * 2 + 1) * Y2S + d];
            float w0 = __ldg(wrow + 0 * 128 + d);
            float w1 = __ldg(wrow + 1 * 128 + d);
            float w2 = __ldg(wrow + 2 * 128 + d);
            float w3 = __ldg(wrow + 3 * 128 + d);
            acc[0][0] = fmaf(a0, w0, acc[0][0]); acc[0][1] = fmaf(a0, w1, acc[0][1]);
            acc[0][2] = fmaf(a0, w2, acc[0][2]); acc[0][3] = fmaf(a0, w3, acc[0][3]);
            acc[1][0] = fmaf(a1, w0, acc[1][0]); acc[1][1] = fmaf(a1, w1, acc[1][1]);
            acc[1][2] = fmaf(a1, w2, acc[1][2]); acc[1][3] = fmaf(a1, w3, acc[1][3]);
        }
        #pragma unroll
        for (int j = 0; j < 4; j++) {
            float bb = __ldg(f1bg + hg * 4 + j);
            hsh[(rg * 2 + 0) * HS + hg * 4 + j] = fmaxf(acc[0][j] + bb, 0.f);
            hsh[(rg * 2 + 1) * HS + hg * 4 + j] = fmaxf(acc[1][j] + bb, 0.f);
        }
    }
    __syncthreads();

    // ---- fc2 + transposed output write: out[b,t,o,n] ----
    if (tid < 160) {
        int r = tid & 31, o = tid >> 5;
        const float* wo = f2wg + o * 64;
        float acc = __ldg(f2bg + o);
        #pragma unroll 8
        for (int j = 0; j < 64; j++)
            acc = fmaf(hsh[r * HS + j], __ldg(wo + j), acc);
        int R  = row0 + r;
        int n  = R % NN;
        int bt = R / NN;
        out[((size_t)bt * 5 + o) * NN + n] = acc;
    }
}

// ---------------------------------------------------------------------------
extern "C" void kernel_launch(void* const* d_in, const int* in_sizes, int n_in,
                              void* d_out, int out_size)
{
    const float* x   = (const float*)d_in[0];
    const float* S   = (const float*)d_in[1];
    const float* w1  = (const float*)d_in[2];
    const float* b1  = (const float*)d_in[3];
    const float* w2  = (const float*)d_in[4];
    const float* b2  = (const float*)d_in[5];
    const float* f1w = (const float*)d_in[6];
    const float* f1b = (const float*)d_in[7];
    const float* f2w = (const float*)d_in[8];
    const float* f2b = (const float*)d_in[9];
    float* out = (float*)d_out;

    // 15 sequential diffusion steps (graph replay amortizes launch cost)
    for (int k = 1; k <= 15; k++)
        diffuse_step_kernel<<<BT, 256>>>(x, S, k);

    size_t smem = (size_t)SMEM_FLOATS * sizeof(float);
    cudaFuncSetAttribute(head_kernel,
                         cudaFuncAttributeMaxDynamicSharedMemorySize, (int)smem);
    head_kernel<<<(NB * NT * NN) / 32, 256, smem>>>(
        x, w1, b1, w2, b2, f1w, f1b, f2w, f2b, out);
}

// round 6
// speedup vs baseline: 1.0743x; 1.0743x over previous
#include <cuda_runtime.h>
#include <cstddef>

// Problem constants
#define NB   16
#define NT   64
#define NF0  8
#define NN   100
#define BT   (NB * NT)            // 1024
#define ROWSTRIDE (NF0 * NN)      // 800 floats per (b,t) slice
#define SLAB ((size_t)BT * ROWSTRIDE)  // 819200 floats per k-slab

// Diffusion scratch: z_k for k = 1..15 at slab k-1.
// Triangular region t<k is never written; head substitutes zeros there.
__device__ float g_z[15 * BT * ROWSTRIDE];   // ~49.15 MB

// ---------------------------------------------------------------------------
// Diffusion step k: z_k[b,t] = z_{k-1}[b,t-1] @ S[b,t]  (skip t<k entirely).
// One block per (b,t), 256 threads (200 active), tile 1 f-row x 4 m-cols.
// S rows streamed as float4, unroll 10 for MLP ~10 (covers L2 ~250cyc).
// ---------------------------------------------------------------------------
__global__ __launch_bounds__(256)
void diffuse_step_kernel(const float* __restrict__ x,
                         const float* __restrict__ S,
                         int k)
{
    int bt  = blockIdx.x;          // b*64 + t
    int t   = bt & 63;
    if (t < k) return;             // zero region: never stored
    int tid = threadIdx.x;

    const float* src = (k == 1)
        ? (x + (size_t)(bt - 1) * ROWSTRIDE)
        : (g_z + (size_t)(k - 2) * SLAB + (size_t)(bt - 1) * ROWSTRIDE);

    __shared__ float Ash[ROWSTRIDE];
    for (int i = tid; i < ROWSTRIDE; i += 256) Ash[i] = src[i];
    __syncthreads();

    if (tid < 200) {
        int mg = tid % 25;                       // m-quad
        int f  = tid / 25;                       // f-row 0..7
        int m0 = mg * 4;
        const float* A0 = Ash + f * NN;
        const float* Sp = S + (size_t)bt * (NN * NN) + m0;

        float a0 = 0.f, a1 = 0.f, a2 = 0.f, a3 = 0.f;
        #pragma unroll 10
        for (int n = 0; n < NN; n++) {
            float4 s = *reinterpret_cast<const float4*>(Sp + (size_t)n * NN);
            float va = A0[n];
            a0 = fmaf(va, s.x, a0); a1 = fmaf(va, s.y, a1);
            a2 = fmaf(va, s.z, a2); a3 = fmaf(va, s.w, a3);
        }
        float* d = g_z + (size_t)(k - 1) * SLAB + (size_t)bt * ROWSTRIDE
                 + f * NN + m0;
        d[0] = a0; d[1] = a1; d[2] = a2; d[3] = a3;
    }
}

// ---------------------------------------------------------------------------
// Fused head: gather z row [8][16] -> conv1(K=4)+relu+pool2 -> [32][6]
//             -> conv2(K=3)+relu+pool2 -> [64][2] -> fc1(128->64)+relu
//             -> fc2(64->5) -> out[b,t,o,n]
// 32 rows/block, 256 threads, 3 blocks/SM (68.6 KB smem, <=84 regs).
// Smem (floats): [0,4128)        zsh (32x129), reused as y2sh
//                [4128,10304)    y1sh (32x193); after conv2: hsh [4128,6208)
//                [10304,11328)   w1   [11328,11360) b1
//                [11360,17504)   w2   [17504,17568) b2
// After conv2, fc weights staged into the dead region starting at 6208:
//   fc1w [6208,14464) stride 129, fc1b [14464,14528),
//   fc2w [14528,14848), fc2b [14848,14853)
// ---------------------------------------------------------------------------
#define ZS   129
#define Y1S  193
#define Y2S  129
#define HS   65
#define OFF_Y1   4128
#define OFF_W1   10304
#define OFF_B1   11328
#define OFF_W2   11360
#define OFF_B2   17504
#define OFF_FC1W 6208
#define OFF_FC1B 14464
#define OFF_FC2W 14528
#define OFF_FC2B 14848
#define SMEM_FLOATS 17568

__global__ __launch_bounds__(256, 3)
void head_kernel(const float* __restrict__ x,
                 const float* __restrict__ w1g, const float* __restrict__ b1g,
                 const float* __restrict__ w2g, const float* __restrict__ b2g,
                 const float* __restrict__ f1wg, const float* __restrict__ f1bg,
                 const float* __restrict__ f2wg, const float* __restrict__ f2bg,
                 float* __restrict__ out)
{
    extern __shared__ float sm[];
    float* zsh  = sm;
    float* y2sh = sm;                 // reuses zsh region after conv1
    float* y1sh = sm + OFF_Y1;
    float* hsh  = sm + OFF_Y1;        // aliases y1sh front (dead after conv2)
    float* w1sh = sm + OFF_W1;
    float* b1sh = sm + OFF_B1;
    float* w2sh = sm + OFF_W2;
    float* b2sh = sm + OFF_B2;

    int tid  = threadIdx.x;
    int row0 = blockIdx.x * 32;       // global row = (b*T + t)*N + n

    // ---- stage 0: gather z tile (32 rows x 8 f x 16 k = 4096) + conv weights ----
    for (int i = tid; i < 4096; i += 256) {
        int r  = i & 31;
        int kf = i >> 5;              // 0..127
        int f  = kf >> 4;             // 0..7
        int k  = kf & 15;             // 0..15
        int R  = row0 + r;
        int n  = R % NN;
        int bt = R / NN;
        float v;
        if (k == 0) {
            v = x[(size_t)bt * ROWSTRIDE + f * NN + n];
        } else if ((bt & 63) < k) {
            v = 0.f;                  // triangular zero region (never stored)
        } else {
            v = g_z[(size_t)(k - 1) * SLAB + (size_t)bt * ROWSTRIDE + f * NN + n];
        }
        zsh[r * ZS + f * 16 + k] = v;
    }
    for (int i = tid; i < 1024; i += 256) w1sh[i] = w1g[i];
    if (tid < 32) b1sh[tid] = b1g[tid];
    for (int i = tid; i < 6144; i += 256) w2sh[i] = w2g[i];
    if (tid < 64) b2sh[tid] = b2g[tid];
    __syncthreads();

    // ---- conv1 + relu + maxpool2 : thread = (r, fg), 2 channels x 2 passes ----
    {
        int r = tid & 31, fg = tid >> 5;         // fg in [0,8)
        #pragma unroll
        for (int p = 0; p < 2; p++) {            // channel-pair pass (reg cap)
            int c0 = fg * 4 + p * 2;             // channels c0, c0+1
            float acc[2][12];
            #pragma unroll
            for (int c = 0; c < 2; c++)
                #pragma unroll
                for (int l = 0; l < 12; l++) acc[c][l] = 0.f;

            #pragma unroll 2
            for (int f0 = 0; f0 < 8; f0++) {
                float a[16];
                #pragma unroll
                for (int i = 0; i < 16; i++) a[i] = zsh[r * ZS + f0 * 16 + i];
                #pragma unroll
                for (int kk = 0; kk < 4; kk++) {
                    #pragma unroll
                    for (int c = 0; c < 2; c++) {
                        float w = w1sh[(c0 + c) * 32 + f0 * 4 + kk];
                        #pragma unroll
                        for (int l = 0; l < 12; l++)
                            acc[c][l] = fmaf(a[l + kk], w, acc[c][l]);
                    }
                }
            }
            #pragma unroll
            for (int c = 0; c < 2; c++) {
                int f1 = c0 + c;
                float bb = b1sh[f1];
                #pragma unroll
                for (int lp = 0; lp < 6; lp++) {
                    float v0 = fmaxf(acc[c][2 * lp]     + bb, 0.f);
                    float v1 = fmaxf(acc[c][2 * lp + 1] + bb, 0.f);
                    y1sh[r * Y1S + f1 * 6 + lp] = fmaxf(v0, v1);
                }
            }
        }
    }
    __syncthreads();

    // ---- conv2 + relu + maxpool2 : thread = (r, 8 channels) ----
    {
        int r = tid & 31, fg = tid >> 5;       // channels fg*8..+7
        float acc[8][4];
        #pragma unroll
        for (int c = 0; c < 8; c++)
            #pragma unroll
            for (int l = 0; l < 4; l++) acc[c][l] = 0.f;

        #pragma unroll 4
        for (int f1 = 0; f1 < 32; f1++) {
            float a[6];
            #pragma unroll
            for (int i = 0; i < 6; i++) a[i] = y1sh[r * Y1S + f1 * 6 + i];
            #pragma unroll
            for (int kk = 0; kk < 3; kk++) {
                #pragma unroll
                for (int c = 0; c < 8; c++) {
                    float w = w2sh[(fg * 8 + c) * 96 + f1 * 3 + kk];
                    #pragma unroll
                    for (int l = 0; l < 4; l++)
                        acc[c][l] = fmaf(a[l + kk], w, acc[c][l]);
                }
            }
        }
        #pragma unroll
        for (int c = 0; c < 8; c++) {
            int f2 = fg * 8 + c;
            float bb = b2sh[f2];
            float v0 = fmaxf(fmaxf(acc[c][0] + bb, 0.f), fmaxf(acc[c][1] + bb, 0.f));
            float v1 = fmaxf(fmaxf(acc[c][2] + bb, 0.f), fmaxf(acc[c][3] + bb, 0.f));
            y2sh[r * Y2S + f2 * 2 + 0] = v0;   // flatten order d = f2*2 + l
            y2sh[r * Y2S + f2 * 2 + 1] = v1;   // (zsh dead since conv1)
        }
    }
    __syncthreads();                           // y1/w1/w2 reads complete

    // ---- stage fc weights into dead region (coalesced, once per block) ----
    {
        float* fc1w = sm + OFF_FC1W;
        for (int i = tid; i < 8192; i += 256) {
            int j = i >> 7, d = i & 127;
            fc1w[j * 129 + d] = f1wg[i];       // padded stride 129 (bank-safe)
        }
        if (tid < 64)  sm[OFF_FC1B + tid] = f1bg[tid];
        if (tid < 5)   sm[OFF_FC2B + tid] = f2bg[tid];
        for (int i = tid; i < 320; i += 256) sm[OFF_FC2W + i] = f2wg[i];
    }
    __syncthreads();

    // ---- fc1 + relu : 256 threads, tile 2 rows x 4 hidden, all smem ----
    {
        const float* fc1w = sm + OFF_FC1W;
        const float* fb   = sm + OFF_FC1B;
        int rg = tid & 15;                     // rows rg*2, rg*2+1
        int hg = tid >> 4;                     // hidden hg*4..+3
        float acc[2][4];
        #pragma unroll
        for (int i = 0; i < 2; i++)
            #pragma unroll
            for (int j = 0; j < 4; j++) acc[i][j] = 0.f;

        #pragma unroll 4
        for (int d = 0; d < 128; d++) {
            float a0 = y2sh[(rg * 2 + 0) * Y2S + d];
            float a1 = y2sh[(rg * 2 + 1) * Y2S + d];
            float w0 = fc1w[(hg * 4 + 0) * 129 + d];
            float w1 = fc1w[(hg * 4 + 1) * 129 + d];
            float w2 = fc1w[(hg * 4 + 2) * 129 + d];
            float w3 = fc1w[(hg * 4 + 3) * 129 + d];
            acc[0][0] = fmaf(a0, w0, acc[0][0]); acc[0][1] = fmaf(a0, w1, acc[0][1]);
            acc[0][2] = fmaf(a0, w2, acc[0][2]); acc[0][3] = fmaf(a0, w3, acc[0][3]);
            acc[1][0] = fmaf(a1, w0, acc[1][0]); acc[1][1] = fmaf(a1, w1, acc[1][1]);
            acc[1][2] = fmaf(a1, w2, acc[1][2]); acc[1][3] = fmaf(a1, w3, acc[1][3]);
        }
        #pragma unroll
        for (int j = 0; j < 4; j++) {
            float bb = fb[hg * 4 + j];
            hsh[(rg * 2 + 0) * HS + hg * 4 + j] = fmaxf(acc[0][j] + bb, 0.f);
            hsh[(rg * 2 + 1) * HS + hg * 4 + j] = fmaxf(acc[1][j] + bb, 0.f);
        }
    }
    __syncthreads();

    // ---- fc2 + transposed output write: out[b,t,o,n] ----
    if (tid < 160) {
        const float* fc2w = sm + OFF_FC2W;
        const float* fc2b = sm + OFF_FC2B;
        int r = tid & 31, o = tid >> 5;
        float acc = fc2b[o];
        #pragma unroll 8
        for (int j = 0; j < 64; j++)
            acc = fmaf(hsh[r * HS + j], fc2w[o * 64 + j], acc);
        int R  = row0 + r;
        int n  = R % NN;
        int bt = R / NN;
        out[((size_t)bt * 5 + o) * NN + n] = acc;
    }
}

// ---------------------------------------------------------------------------
extern "C" void kernel_launch(void* const* d_in, const int* in_sizes, int n_in,
                              void* d_out, int out_size)
{
    const float* x   = (const float*)d_in[0];
    const float* S   = (const float*)d_in[1];
    const float* w1  = (const float*)d_in[2];
    const float* b1  = (const float*)d_in[3];
    const float* w2  = (const float*)d_in[4];
    const float* b2  = (const float*)d_in[5];
    const float* f1w = (const float*)d_in[6];
    const float* f1b = (const float*)d_in[7];
    const float* f2w = (const float*)d_in[8];
    const float* f2b = (const float*)d_in[9];
    float* out = (float*)d_out;

    // 15 sequential diffusion steps (graph replay amortizes launch cost)
    for (int k = 1; k <= 15; k++)
        diffuse_step_kernel<<<BT, 256>>>(x, S, k);

    size_t smem = (size_t)SMEM_FLOATS * sizeof(float);
    cudaFuncSetAttribute(head_kernel,
                         cudaFuncAttributeMaxDynamicSharedMemorySize, (int)smem);
    head_kernel<<<(NB * NT * NN) / 32, 256, smem>>>(
        x, w1, b1, w2, b2, f1w, f1b, f2w, f2b, out);
}